// round 1
// baseline (speedup 1.0000x reference)
#include <cuda_runtime.h>
#include <cuda_bf16.h>
#include <math_constants.h>

// Problem shapes (fixed by setup_inputs)
#define B  4
#define N  16384
#define S  4096
#define C  256
#define K_NN 3

// Scratch: per-query top-3 weights + indices (allocation-free rule -> device globals)
__device__ float g_w[B * N * K_NN];
__device__ int   g_i[B * N * K_NN];

// ---------------------------------------------------------------------------
// Phase 1: brute-force 3-NN. 1 thread = 1 query. Keys cached in smem as float4
// (x, y, z, ||k||^2). d = qq + kk - 2*q.k via 3 FFMA + 1 FADD per key.
// ---------------------------------------------------------------------------
__global__ void knn_kernel(const float* __restrict__ q,
                           const float* __restrict__ k)
{
    extern __shared__ float4 k4[];   // S entries = 64 KB

    const int b = blockIdx.y;
    const int n = blockIdx.x * blockDim.x + threadIdx.x;

    // Cooperative load of k[b] into smem, computing ||k||^2 on the fly.
    const float* kb = k + b * S * 3;
    for (int s = threadIdx.x; s < S; s += blockDim.x) {
        float kx = kb[3 * s + 0];
        float ky = kb[3 * s + 1];
        float kz = kb[3 * s + 2];
        k4[s] = make_float4(kx, ky, kz, fmaf(kx, kx, fmaf(ky, ky, kz * kz)));
    }
    __syncthreads();

    const float* qp = q + ((size_t)b * N + n) * 3;
    const float qx = qp[0], qy = qp[1], qz = qp[2];
    const float qq = fmaf(qx, qx, fmaf(qy, qy, qz * qz));
    const float ax = -2.0f * qx, ay = -2.0f * qy, az = -2.0f * qz;

    float d0 = CUDART_INF_F, d1 = CUDART_INF_F, d2 = CUDART_INF_F;
    int   i0 = 0, i1 = 0, i2 = 0;

#pragma unroll 4
    for (int s = 0; s < S; ++s) {
        const float4 kv = k4[s];
        const float d = fmaf(ax, kv.x, fmaf(ay, kv.y, fmaf(az, kv.z, qq + kv.w)));
        if (d < d2) {                       // rare path (~25 hits over 4096 keys)
            if (d < d1) {
                d2 = d1; i2 = i1;
                if (d < d0) { d1 = d0; i1 = i0; d0 = d; i0 = s; }
                else        { d1 = d;  i1 = s; }
            } else {
                d2 = d; i2 = s;
            }
        }
    }

    const float r0 = 1.0f / (d0 + 1e-8f);
    const float r1 = 1.0f / (d1 + 1e-8f);
    const float r2 = 1.0f / (d2 + 1e-8f);
    const float inv = 1.0f / (r0 + r1 + r2);

    const int base = (b * N + n) * K_NN;
    g_w[base + 0] = r0 * inv;
    g_w[base + 1] = r1 * inv;
    g_w[base + 2] = r2 * inv;
    g_i[base + 0] = i0;
    g_i[base + 1] = i1;
    g_i[base + 2] = i2;
}

// ---------------------------------------------------------------------------
// Phase 2: weighted gather of v rows + transpose to out[b][c][n].
// Block = 32-query tile. Coalesced 1KB row reads of v, smem transpose
// (pad 257 -> conflict-free), 128B-contiguous writes along n.
// ---------------------------------------------------------------------------
#define NQ 32

__global__ void gather_kernel(const float* __restrict__ v,
                              float* __restrict__ out)
{
    __shared__ float buf[NQ][C + 1];   // +1 pad: transpose reads conflict-free
    __shared__ float w[NQ * K_NN];
    __shared__ int   id[NQ * K_NN];

    const int b   = blockIdx.y;
    const int n0  = blockIdx.x * NQ;
    const int tid = threadIdx.x;       // 256 threads

    if (tid < NQ * K_NN) {
        const int base = (b * N + n0) * K_NN;
        w[tid]  = g_w[base + tid];
        id[tid] = g_i[base + tid];
    }
    __syncthreads();

    const float* vb = v + (size_t)b * S * C;

    // Gather: one query per iteration, 256 threads cover all channels.
#pragma unroll 4
    for (int ql = 0; ql < NQ; ++ql) {
        const int   j0 = id[ql * 3 + 0], j1 = id[ql * 3 + 1], j2 = id[ql * 3 + 2];
        const float w0 = w[ql * 3 + 0],  w1 = w[ql * 3 + 1],  w2 = w[ql * 3 + 2];
        const float a0 = vb[j0 * C + tid];
        const float a1 = vb[j1 * C + tid];
        const float a2 = vb[j2 * C + tid];
        buf[ql][tid] = fmaf(w0, a0, fmaf(w1, a1, w2 * a2));
    }
    __syncthreads();

    // Transposed write: warp 'wr' handles channel rows wr, wr+8, ...; lanes
    // cover 32 consecutive n -> 128B contiguous stores.
    const int warp = tid >> 5;
    const int lane = tid & 31;
    float* ob = out + (size_t)b * C * N + n0;
#pragma unroll
    for (int c = warp; c < C; c += 8) {
        ob[c * N + lane] = buf[lane][c];
    }
}

// ---------------------------------------------------------------------------
extern "C" void kernel_launch(void* const* d_in, const int* in_sizes, int n_in,
                              void* d_out, int out_size)
{
    const float* q = (const float*)d_in[0];   // (B, N, 3)
    const float* k = (const float*)d_in[1];   // (B, S, 3)
    const float* v = (const float*)d_in[2];   // (B, S, C)
    float* out = (float*)d_out;               // (B, C, N)

    static_assert(S * sizeof(float4) == 65536, "smem size");
    cudaFuncSetAttribute(knn_kernel,
                         cudaFuncAttributeMaxDynamicSharedMemorySize, 65536);

    dim3 g1(N / 256, B);
    knn_kernel<<<g1, 256, 65536>>>(q, k);

    dim3 g2(N / NQ, B);
    gather_kernel<<<g2, 256>>>(v, out);
}

// round 2
// speedup vs baseline: 1.2214x; 1.2214x over previous
#include <cuda_runtime.h>
#include <math_constants.h>
#include <cstdint>

#define B  4
#define N  16384
#define S  4096
#define C  256
#define K_NN 3

#define CHUNKS 4
#define SKEYS  (S / CHUNKS)     // 1024 keys per chunk
#define SPAIRS (SKEYS / 2)      // 512 pairs
#define QT     256              // queries per knn block

// Scratch (allocation-free rule -> device globals): per-chunk partial top-3
__device__ float p_d[B * N * CHUNKS * 3];
__device__ int   p_i[B * N * CHUNKS * 3];

// ---------------------------------------------------------------------------
// f32x2 packed helpers (sm_103a FFMA2/FADD2 — ptxas only emits via PTX f32x2)
// ---------------------------------------------------------------------------
__device__ __forceinline__ uint64_t fma2_(uint64_t a, uint64_t b, uint64_t c) {
    uint64_t d;
    asm("fma.rn.f32x2 %0, %1, %2, %3;" : "=l"(d) : "l"(a), "l"(b), "l"(c));
    return d;
}
__device__ __forceinline__ uint64_t add2_(uint64_t a, uint64_t b) {
    uint64_t d;
    asm("add.rn.f32x2 %0, %1, %2;" : "=l"(d) : "l"(a), "l"(b));
    return d;
}
__device__ __forceinline__ uint64_t pack2_(float lo, float hi) {
    uint64_t d;
    asm("mov.b64 %0, {%1, %2};" : "=l"(d) : "f"(lo), "f"(hi));
    return d;
}
__device__ __forceinline__ void unpack2_(uint64_t v, float& lo, float& hi) {
    asm("mov.b64 {%0, %1}, %2;" : "=f"(lo), "=f"(hi) : "l"(v));
}

// Strict-< insert keeps earliest index on ties (matches jax.lax.top_k)
#define INSERT(d, s) do {                                            \
    if ((d) < d1) {                                                  \
        d2 = d1; i2 = i1;                                            \
        if ((d) < d0) { d1 = d0; i1 = i0; d0 = (d); i0 = (s); }      \
        else          { d1 = (d); i1 = (s); }                        \
    } else { d2 = (d); i2 = (s); }                                   \
} while (0)

// ---------------------------------------------------------------------------
// Phase 1: brute-force partial 3-NN over a 1024-key chunk.
// Keys in smem as packed pairs: kp[2p] = {x2,y2}, kp[2p+1] = {z2,w2}
// Hot path per pair: 2 LDS.128 + 1 FADD2 + 3 FFMA2 + FMNMX + FSETP + rare BRA
// ---------------------------------------------------------------------------
__global__ void __launch_bounds__(QT) knn_kernel(const float* __restrict__ q,
                                                 const float* __restrict__ k)
{
    __shared__ ulonglong2 kp[SPAIRS * 2];   // 16 KB

    const int b     = blockIdx.z;
    const int chunk = blockIdx.y;
    const int n     = blockIdx.x * QT + threadIdx.x;

    // Cooperative load: build packed pair layout + ||k||^2
    const float* kb = k + ((size_t)b * S + (size_t)chunk * SKEYS) * 3;
    for (int p = threadIdx.x; p < SPAIRS; p += QT) {
        float x0 = kb[6 * p + 0], y0 = kb[6 * p + 1], z0 = kb[6 * p + 2];
        float x1 = kb[6 * p + 3], y1 = kb[6 * p + 4], z1 = kb[6 * p + 5];
        float w0 = fmaf(x0, x0, fmaf(y0, y0, z0 * z0));
        float w1 = fmaf(x1, x1, fmaf(y1, y1, z1 * z1));
        kp[2 * p]     = make_ulonglong2(pack2_(x0, x1), pack2_(y0, y1));
        kp[2 * p + 1] = make_ulonglong2(pack2_(z0, z1), pack2_(w0, w1));
    }
    __syncthreads();

    const float* qp = q + ((size_t)b * N + n) * 3;
    const float qx = qp[0], qy = qp[1], qz = qp[2];
    const float qq = fmaf(qx, qx, fmaf(qy, qy, qz * qz));
    const uint64_t ax2 = pack2_(-2.0f * qx, -2.0f * qx);
    const uint64_t ay2 = pack2_(-2.0f * qy, -2.0f * qy);
    const uint64_t az2 = pack2_(-2.0f * qz, -2.0f * qz);
    const uint64_t qq2 = pack2_(qq, qq);

    float d0 = CUDART_INF_F, d1 = CUDART_INF_F, d2 = CUDART_INF_F;
    int   i0 = 0, i1 = 0, i2 = 0;

#pragma unroll 4
    for (int p = 0; p < SPAIRS; ++p) {
        const ulonglong2 A = kp[2 * p];       // x-pair, y-pair
        const ulonglong2 Z = kp[2 * p + 1];   // z-pair, w-pair
        uint64_t t = add2_(qq2, Z.y);
        t = fma2_(az2, Z.x, t);
        t = fma2_(ay2, A.y, t);
        t = fma2_(ax2, A.x, t);
        float ta, tb;
        unpack2_(t, ta, tb);
        if (fminf(ta, tb) < d2) {             // rare: ~1% of pair-iters per lane
            if (ta < d2) { INSERT(ta, 2 * p); }
            if (tb < d2) { INSERT(tb, 2 * p + 1); }
        }
    }

    const int base = ((b * N + n) * CHUNKS + chunk) * 3;
    const int off  = chunk * SKEYS;
    p_d[base + 0] = d0;  p_i[base + 0] = i0 + off;
    p_d[base + 1] = d1;  p_i[base + 1] = i1 + off;
    p_d[base + 2] = d2;  p_i[base + 2] = i2 + off;
}

// ---------------------------------------------------------------------------
// Phase 2: merge partial top-3 (32 threads) + weighted gather + transpose.
// v rows read as float4 (coalesced 1KB rows, L2-resident). Output written
// 128B-contiguous per channel row.
// ---------------------------------------------------------------------------
#define NQ 32

__global__ void __launch_bounds__(256) gather_kernel(const float* __restrict__ v,
                                                     float* __restrict__ out)
{
    __shared__ float buf[NQ][C + 4];   // row stride 260 floats: 16B-aligned rows
    __shared__ float w[NQ * 3];
    __shared__ int   id[NQ * 3];

    const int b   = blockIdx.y;
    const int n0  = blockIdx.x * NQ;
    const int tid = threadIdx.x;       // 256 threads

    if (tid < NQ) {
        // Merge CHUNKS partial sorted triples (chunk order = ascending index
        // ranges, strict-< insert => top_k tie semantics preserved)
        const int base = ((b * N + n0 + tid) * CHUNKS) * 3;
        float d0 = p_d[base + 0], d1 = p_d[base + 1], d2 = p_d[base + 2];
        int   i0 = p_i[base + 0], i1 = p_i[base + 1], i2 = p_i[base + 2];
#pragma unroll
        for (int c = 1; c < CHUNKS; ++c)
#pragma unroll
            for (int j = 0; j < 3; ++j) {
                const float d = p_d[base + c * 3 + j];
                const int   s = p_i[base + c * 3 + j];
                if (d < d2) { INSERT(d, s); }
            }
        const float r0 = 1.0f / (d0 + 1e-8f);
        const float r1 = 1.0f / (d1 + 1e-8f);
        const float r2 = 1.0f / (d2 + 1e-8f);
        const float inv = 1.0f / (r0 + r1 + r2);
        w[tid * 3 + 0] = r0 * inv;  id[tid * 3 + 0] = i0;
        w[tid * 3 + 1] = r1 * inv;  id[tid * 3 + 1] = i1;
        w[tid * 3 + 2] = r2 * inv;  id[tid * 3 + 2] = i2;
    }
    __syncthreads();

    const float4* vb4 = (const float4*)(v + (size_t)b * S * C);
    const int c4 = tid & 63;          // float4 channel slot (64 per row)
    const int qo = tid >> 6;          // 4 queries handled per iteration

#pragma unroll
    for (int qb = 0; qb < NQ; qb += 4) {
        const int ql = qb + qo;
        const int   j0 = id[ql * 3 + 0], j1 = id[ql * 3 + 1], j2 = id[ql * 3 + 2];
        const float w0 = w[ql * 3 + 0],  w1 = w[ql * 3 + 1],  w2 = w[ql * 3 + 2];
        const float4 a0 = vb4[j0 * 64 + c4];
        const float4 a1 = vb4[j1 * 64 + c4];
        const float4 a2 = vb4[j2 * 64 + c4];
        float4 r;
        r.x = fmaf(w0, a0.x, fmaf(w1, a1.x, w2 * a2.x));
        r.y = fmaf(w0, a0.y, fmaf(w1, a1.y, w2 * a2.y));
        r.z = fmaf(w0, a0.z, fmaf(w1, a1.z, w2 * a2.z));
        r.w = fmaf(w0, a0.w, fmaf(w1, a1.w, w2 * a2.w));
        *(float4*)&buf[ql][c4 * 4] = r;   // STS.128 (rows 16B-aligned)
    }
    __syncthreads();

    // Transposed write: warp -> channel rows, lanes -> 32 consecutive n
    const int warp = tid >> 5;
    const int lane = tid & 31;
    float* ob = out + (size_t)b * C * N + n0;
#pragma unroll
    for (int c = warp; c < C; c += 8)
        ob[c * N + lane] = buf[lane][c];
}

// ---------------------------------------------------------------------------
extern "C" void kernel_launch(void* const* d_in, const int* in_sizes, int n_in,
                              void* d_out, int out_size)
{
    const float* q = (const float*)d_in[0];   // (B, N, 3)
    const float* k = (const float*)d_in[1];   // (B, S, 3)
    const float* v = (const float*)d_in[2];   // (B, S, C)
    float* out = (float*)d_out;               // (B, C, N)

    dim3 g1(N / QT, CHUNKS, B);               // 64 x 4 x 4 = 1024 blocks
    knn_kernel<<<g1, QT>>>(q, k);

    dim3 g2(N / NQ, B);                       // 512 x 4 = 2048 blocks
    gather_kernel<<<g2, 256>>>(v, out);
}